// round 4
// baseline (speedup 1.0000x reference)
#include <cuda_runtime.h>
#include <cuda_fp16.h>

#define N_USERS 40000
#define N_ITEMS 60000
#define N_NODES 100000
#define N_EDGES 1280000
#define EMB 64
#define NEG_SLOPE 0.2f

// ---------------- scratch (static device globals; no allocs) ----------------
__device__ float  g_e[N_NODES * EMB];      // current layer embeddings (fp32)
__device__ __half g_eh[N_NODES * EMB];     // fp16 shadow for SpMM gather
__device__ float  g_x[N_NODES * EMB];      // spmm result
__device__ float  g_acc[N_NODES * EMB];    // running sum
__device__ int    g_rowptr[N_NODES + 1];
__device__ int    g_cursor[N_NODES];       // counts, then scatter cursors
__device__ int    g_bsum[256];             // scan block sums
__device__ int    g_cols[N_EDGES];
__device__ float  g_vals[N_EDGES];

// ---------------- packed f32x2 helpers (sm_103a FFMA2 path) ----------------
#define FMA_F32X2(out, a, b, c) \
    asm("fma.rn.f32x2 %0, %1, %2, %3;" : "=l"(out) : "l"(a), "l"(b), "l"(c))
#define PACK_F32X2(out, lo, hi) \
    asm("mov.b64 %0, {%1, %2};" : "=l"(out) : "r"(lo), "r"(hi))
#define UNPACK_F32X2(lo, hi, in) \
    asm("mov.b64 {%0, %1}, %2;" : "=r"(lo), "=r"(hi) : "l"(in))

// -------- init: e = acc = concat(user,item); eh = fp16(e); zero counters ----
__global__ void k_init(const float* __restrict__ user, const float* __restrict__ item) {
    int i = blockIdx.x * blockDim.x + threadIdx.x;           // float4 index
    if (i < N_NODES) g_cursor[i] = 0;
    const int total4 = (N_NODES * EMB) / 4;
    if (i >= total4) return;
    const int u4 = (N_USERS * EMB) / 4;
    float4 v = (i < u4) ? ((const float4*)user)[i] : ((const float4*)item)[i - u4];
    ((float4*)g_e)[i]   = v;
    ((float4*)g_acc)[i] = v;
    __half2 h0 = __floats2half2_rn(v.x, v.y);
    __half2 h1 = __floats2half2_rn(v.z, v.w);
    ((__half2*)g_eh)[i * 2]     = h0;
    ((__half2*)g_eh)[i * 2 + 1] = h1;
}

// ---------------- CSR build ----------------
__global__ void k_hist(const int* __restrict__ row) {
    int i = blockIdx.x * blockDim.x + threadIdx.x;
    if (i < N_EDGES) atomicAdd(&g_cursor[row[i]], 1);
}

// pass 1: per-block inclusive scan of 512-element chunk; write exclusive partials
__global__ void k_scan1() {
    __shared__ int s[512];
    int t = threadIdx.x;
    int idx = blockIdx.x * 512 + t;
    int val = (idx < N_NODES) ? g_cursor[idx] : 0;
    s[t] = val;
    __syncthreads();
    #pragma unroll
    for (int off = 1; off < 512; off <<= 1) {
        int v = (t >= off) ? s[t - off] : 0;
        __syncthreads();
        s[t] += v;
        __syncthreads();
    }
    if (idx < N_NODES) g_rowptr[idx] = s[t] - val;  // exclusive partial
    if (t == 511) g_bsum[blockIdx.x] = s[511];
}

// pass 2+3 fused: each block reduces bsum[0..b) itself, then adds offsets
__global__ void k_scan3() {
    __shared__ int sred[512];
    int t = threadIdx.x;
    int b = blockIdx.x;
    sred[t] = (t < b) ? g_bsum[t] : 0;
    __syncthreads();
    #pragma unroll
    for (int off = 256; off; off >>= 1) {
        if (t < off) sred[t] += sred[t + off];
        __syncthreads();
    }
    int base = sred[0];
    int idx = b * 512 + t;
    if (idx < N_NODES) {
        int v = g_rowptr[idx] + base;
        g_rowptr[idx] = v;
        g_cursor[idx] = v;
    }
    if (idx == 0) g_rowptr[N_NODES] = N_EDGES;
}

__global__ void k_scatter(const int* __restrict__ row, const int* __restrict__ col,
                          const float* __restrict__ val) {
    int i = blockIdx.x * blockDim.x + threadIdx.x;
    if (i >= N_EDGES) return;
    int r = row[i];
    int pos = atomicAdd(&g_cursor[r], 1);
    g_cols[pos] = col[i];
    g_vals[pos] = val[i];
}

// ------- SpMM: x[r] = sum_j val_j * e[col_j]  (warp/row, fp16 gather) -------
__global__ void k_spmm() {
    int r = blockIdx.x * 8 + (threadIdx.x >> 5);
    if (r >= N_NODES) return;
    int lane = threadIdx.x & 31;
    int s = g_rowptr[r];
    int t = g_rowptr[r + 1];
    float ax0 = 0.f, ay0 = 0.f, ax1 = 0.f, ay1 = 0.f;
    int j = s;
    for (; j + 1 < t; j += 2) {
        int   c0 = g_cols[j];
        int   c1 = g_cols[j + 1];
        float v0 = g_vals[j];
        float v1 = g_vals[j + 1];
        float2 e0 = __half22float2(*(const __half2*)&g_eh[c0 * EMB + lane * 2]);
        float2 e1 = __half22float2(*(const __half2*)&g_eh[c1 * EMB + lane * 2]);
        ax0 = fmaf(v0, e0.x, ax0);
        ay0 = fmaf(v0, e0.y, ay0);
        ax1 = fmaf(v1, e1.x, ax1);
        ay1 = fmaf(v1, e1.y, ay1);
    }
    if (j < t) {
        int   c = g_cols[j];
        float v = g_vals[j];
        float2 ev = __half22float2(*(const __half2*)&g_eh[c * EMB + lane * 2]);
        ax0 = fmaf(v, ev.x, ax0);
        ay0 = fmaf(v, ev.y, ay0);
    }
    *(float2*)&g_x[r * EMB + lane * 2] = make_float2(ax0 + ax1, ay0 + ay1);
}

// ---------------- Dense: h = (e+x)@W1 + (x*e)@W2 + b1+b2; leaky; l2norm ------
// block: 256 threads, 128-node tile. thread tile: 4 nodes x 8 cols (4 f32x2 accs).
// dynamic smem: sA1[128*65] sA2[128*65] sW1[4096] sW2[4096]  = 99328 B
#define A_STRIDE 65
__global__ void __launch_bounds__(256, 2)
k_dense(const float* __restrict__ W1, const float* __restrict__ b1,
        const float* __restrict__ W2, const float* __restrict__ b2,
        float* __restrict__ out, int last) {
    extern __shared__ float sm[];
    float* sA1 = sm;                       // 128*65
    float* sA2 = sm + 128 * A_STRIDE;      // 128*65
    float* sW1 = sm + 2 * 128 * A_STRIDE;  // 4096
    float* sW2 = sW1 + 4096;               // 4096

    const int node0 = blockIdx.x * 128;
    const int tid = threadIdx.x;

    for (int i = tid; i < 1024; i += 256) {
        ((float4*)sW1)[i] = ((const float4*)W1)[i];
        ((float4*)sW2)[i] = ((const float4*)W2)[i];
    }
    for (int i = tid; i < 2048; i += 256) {
        int r  = i >> 4;
        int c4 = (i & 15) * 4;
        int n  = node0 + r;
        float4 ev = make_float4(0.f, 0.f, 0.f, 0.f);
        float4 xv = ev;
        if (n < N_NODES) {
            ev = *(const float4*)&g_e[n * EMB + c4];
            xv = *(const float4*)&g_x[n * EMB + c4];
        }
        float* p1 = &sA1[r * A_STRIDE + c4];
        float* p2 = &sA2[r * A_STRIDE + c4];
        p1[0] = ev.x + xv.x; p1[1] = ev.y + xv.y; p1[2] = ev.z + xv.z; p1[3] = ev.w + xv.w;
        p2[0] = ev.x * xv.x; p2[1] = ev.y * xv.y; p2[2] = ev.z * xv.z; p2[3] = ev.w * xv.w;
    }
    __syncthreads();

    const int tn = (tid >> 3) * 4;   // node base in tile (0..124)
    const int tk = (tid & 7) * 8;    // col base (0..56)

    unsigned long long racc[4][4];   // 4 nodes x 4 packed col-pairs
    #pragma unroll
    for (int i = 0; i < 4; i++)
        #pragma unroll
        for (int p = 0; p < 4; p++) racc[i][p] = 0ull;

    #pragma unroll 2
    for (int d = 0; d < 64; d++) {
        const unsigned long long* w1p = (const unsigned long long*)&sW1[d * 64 + tk];
        const unsigned long long* w2p = (const unsigned long long*)&sW2[d * 64 + tk];
        unsigned long long w1_0 = w1p[0], w1_1 = w1p[1], w1_2 = w1p[2], w1_3 = w1p[3];
        unsigned long long w2_0 = w2p[0], w2_1 = w2p[1], w2_2 = w2p[2], w2_3 = w2p[3];
        #pragma unroll
        for (int i = 0; i < 4; i++) {
            float a1 = sA1[(tn + i) * A_STRIDE + d];
            float a2 = sA2[(tn + i) * A_STRIDE + d];
            unsigned int a1u = __float_as_uint(a1);
            unsigned int a2u = __float_as_uint(a2);
            unsigned long long a1p, a2p;
            PACK_F32X2(a1p, a1u, a1u);
            PACK_F32X2(a2p, a2u, a2u);
            FMA_F32X2(racc[i][0], a1p, w1_0, racc[i][0]);
            FMA_F32X2(racc[i][1], a1p, w1_1, racc[i][1]);
            FMA_F32X2(racc[i][2], a1p, w1_2, racc[i][2]);
            FMA_F32X2(racc[i][3], a1p, w1_3, racc[i][3]);
            FMA_F32X2(racc[i][0], a2p, w2_0, racc[i][0]);
            FMA_F32X2(racc[i][1], a2p, w2_1, racc[i][1]);
            FMA_F32X2(racc[i][2], a2p, w2_2, racc[i][2]);
            FMA_F32X2(racc[i][3], a2p, w2_3, racc[i][3]);
        }
    }

    // bias + leaky relu, stage h back into sA1 (reuse)
    float bs[8];
    #pragma unroll
    for (int j = 0; j < 8; j++) bs[j] = b1[tk + j] + b2[tk + j];
    __syncthreads();   // all reads of sA1/sA2 complete before overwrite
    #pragma unroll
    for (int i = 0; i < 4; i++) {
        #pragma unroll
        for (int p = 0; p < 4; p++) {
            unsigned int lo, hi;
            UNPACK_F32X2(lo, hi, racc[i][p]);
            float h0 = __uint_as_float(lo) + bs[2 * p];
            float h1 = __uint_as_float(hi) + bs[2 * p + 1];
            h0 = (h0 >= 0.f) ? h0 : NEG_SLOPE * h0;
            h1 = (h1 >= 0.f) ? h1 : NEG_SLOPE * h1;
            sA1[(tn + i) * A_STRIDE + tk + 2 * p]     = h0;
            sA1[(tn + i) * A_STRIDE + tk + 2 * p + 1] = h1;
        }
    }
    __syncthreads();

    // per-row L2 normalize + update e, eh, acc (+ final output on last layer)
    int w = tid >> 5, lane = tid & 31;
    for (int rr = w; rr < 128; rr += 8) {
        int n = node0 + rr;
        float h0 = sA1[rr * A_STRIDE + lane * 2];
        float h1 = sA1[rr * A_STRIDE + lane * 2 + 1];
        float ss = h0 * h0 + h1 * h1;
        #pragma unroll
        for (int off = 16; off; off >>= 1) ss += __shfl_xor_sync(0xffffffffu, ss, off);
        float scale = 1.0f / fmaxf(sqrtf(ss), 1e-12f);
        if (n < N_NODES) {
            float e0 = h0 * scale, e1 = h1 * scale;
            float2 a = *(const float2*)&g_acc[n * EMB + lane * 2];
            float a0 = a.x + e0, a1 = a.y + e1;
            *(float2*)&g_e[n * EMB + lane * 2] = make_float2(e0, e1);
            *(__half2*)&g_eh[n * EMB + lane * 2] = __floats2half2_rn(e0, e1);
            if (last) {
                *(float2*)&out[n * EMB + lane * 2] = make_float2(a0 * 0.25f, a1 * 0.25f);
            } else {
                *(float2*)&g_acc[n * EMB + lane * 2] = make_float2(a0, a1);
            }
        }
    }
}

// ---------------- launch ----------------
extern "C" void kernel_launch(void* const* d_in, const int* in_sizes, int n_in,
                              void* d_out, int out_size) {
    const int*   edge_row = (const int*)d_in[0];
    const int*   edge_col = (const int*)d_in[1];
    const float* edge_val = (const float*)d_in[2];
    const float* user_emb = (const float*)d_in[3];
    const float* item_emb = (const float*)d_in[4];
    const float* W1 = (const float*)d_in[5];
    const float* b1 = (const float*)d_in[6];
    const float* W2 = (const float*)d_in[7];
    const float* b2 = (const float*)d_in[8];
    float* out = (float*)d_out;

    const int dense_smem = (2 * 128 * A_STRIDE + 2 * 4096) * (int)sizeof(float); // 99328 B
    cudaFuncSetAttribute(k_dense, cudaFuncAttributeMaxDynamicSharedMemorySize, dense_smem);

    const int scan_blocks = (N_NODES + 511) / 512;  // 196

    k_init<<<(N_NODES * EMB / 4 + 255) / 256, 256>>>(user_emb, item_emb);
    k_hist<<<(N_EDGES + 255) / 256, 256>>>(edge_row);
    k_scan1<<<scan_blocks, 512>>>();
    k_scan3<<<scan_blocks, 512>>>();
    k_scatter<<<(N_EDGES + 255) / 256, 256>>>(edge_row, edge_col, edge_val);

    for (int layer = 0; layer < 3; layer++) {
        k_spmm<<<(N_NODES + 7) / 8, 256>>>();
        k_dense<<<(N_NODES + 127) / 128, 256, dense_smem>>>(
            W1 + layer * EMB * EMB, b1 + layer * EMB,
            W2 + layer * EMB * EMB, b2 + layer * EMB,
            out, layer == 2);
    }
    (void)in_sizes; (void)n_in; (void)out_size;
}

// round 15
// speedup vs baseline: 1.0519x; 1.0519x over previous
#include <cuda_runtime.h>
#include <cuda_fp16.h>

#define N_USERS 40000
#define N_ITEMS 60000
#define N_NODES 100000
#define N_EDGES 1280000
#define EMB 64
#define NEG_SLOPE 0.2f

// ---------------- scratch (static device globals; no allocs) ----------------
__device__ float  g_e[N_NODES * EMB];      // current layer embeddings (fp32)
__device__ __half g_eh[N_NODES * EMB];     // fp16 shadow for SpMM gather
__device__ float  g_x[N_NODES * EMB];      // spmm result
__device__ float  g_acc[N_NODES * EMB];    // running sum
__device__ int    g_rowptr[N_NODES + 1];
__device__ int    g_cursor[N_NODES];       // counts, then scatter cursors
__device__ int    g_bsum[256];             // scan block sums
__device__ int2   g_edge[N_EDGES];         // packed (col, val-bits)

// ---------------- packed f32x2 helpers (sm_103a FFMA2 path) ----------------
#define FMA_F32X2(out, a, b, c) \
    asm("fma.rn.f32x2 %0, %1, %2, %3;" : "=l"(out) : "l"(a), "l"(b), "l"(c))
#define UNPACK_F32X2(lo, hi, in) \
    asm("mov.b64 {%0, %1}, %2;" : "=r"(lo), "=r"(hi) : "l"(in))

// -------- init: e = acc = concat(user,item); eh = fp16(e); zero counters ----
__global__ void k_init(const float* __restrict__ user, const float* __restrict__ item) {
    int i = blockIdx.x * blockDim.x + threadIdx.x;           // float4 index
    if (i < N_NODES) g_cursor[i] = 0;
    const int total4 = (N_NODES * EMB) / 4;
    if (i >= total4) return;
    const int u4 = (N_USERS * EMB) / 4;
    float4 v = (i < u4) ? ((const float4*)user)[i] : ((const float4*)item)[i - u4];
    ((float4*)g_e)[i]   = v;
    ((float4*)g_acc)[i] = v;
    __half2 h0 = __floats2half2_rn(v.x, v.y);
    __half2 h1 = __floats2half2_rn(v.z, v.w);
    ((__half2*)g_eh)[i * 2]     = h0;
    ((__half2*)g_eh)[i * 2 + 1] = h1;
}

// ---------------- CSR build ----------------
__global__ void k_hist(const int* __restrict__ row) {
    int i = blockIdx.x * blockDim.x + threadIdx.x;
    if (i < N_EDGES) atomicAdd(&g_cursor[row[i]], 1);
}

__global__ void k_scan1() {
    __shared__ int s[512];
    int t = threadIdx.x;
    int idx = blockIdx.x * 512 + t;
    int val = (idx < N_NODES) ? g_cursor[idx] : 0;
    s[t] = val;
    __syncthreads();
    #pragma unroll
    for (int off = 1; off < 512; off <<= 1) {
        int v = (t >= off) ? s[t - off] : 0;
        __syncthreads();
        s[t] += v;
        __syncthreads();
    }
    if (idx < N_NODES) g_rowptr[idx] = s[t] - val;  // exclusive partial
    if (t == 511) g_bsum[blockIdx.x] = s[511];
}

// pass 2+3 fused: each block reduces bsum[0..b) itself, then adds offsets
__global__ void k_scan3() {
    __shared__ int sred[512];
    int t = threadIdx.x;
    int b = blockIdx.x;
    sred[t] = (t < b) ? g_bsum[t] : 0;
    __syncthreads();
    #pragma unroll
    for (int off = 256; off; off >>= 1) {
        if (t < off) sred[t] += sred[t + off];
        __syncthreads();
    }
    int base = sred[0];
    int idx = b * 512 + t;
    if (idx < N_NODES) {
        int v = g_rowptr[idx] + base;
        g_rowptr[idx] = v;
        g_cursor[idx] = v;
    }
    if (idx == 0) g_rowptr[N_NODES] = N_EDGES;
}

__global__ void k_scatter(const int* __restrict__ row, const int* __restrict__ col,
                          const float* __restrict__ val) {
    int i = blockIdx.x * blockDim.x + threadIdx.x;
    if (i >= N_EDGES) return;
    int r = row[i];
    int pos = atomicAdd(&g_cursor[r], 1);
    g_edge[pos] = make_int2(col[i], __float_as_int(val[i]));   // single 8B write
}

// --- SpMM: x[r] = sum_j val_j * e[col_j]  (warp/row, fp16 gather, MLP=4) ---
__global__ void k_spmm() {
    int r = blockIdx.x * 8 + (threadIdx.x >> 5);
    if (r >= N_NODES) return;
    int lane = threadIdx.x & 31;
    int s = g_rowptr[r];
    int t = g_rowptr[r + 1];
    float ax0 = 0.f, ay0 = 0.f, ax1 = 0.f, ay1 = 0.f;
    float ax2 = 0.f, ay2 = 0.f, ax3 = 0.f, ay3 = 0.f;
    int j = s;
    for (; j + 3 < t; j += 4) {
        int2 p0 = g_edge[j],     p1 = g_edge[j + 1];
        int2 p2 = g_edge[j + 2], p3 = g_edge[j + 3];
        float v0 = __int_as_float(p0.y), v1 = __int_as_float(p1.y);
        float v2 = __int_as_float(p2.y), v3 = __int_as_float(p3.y);
        float2 e0 = __half22float2(*(const __half2*)&g_eh[p0.x * EMB + lane * 2]);
        float2 e1 = __half22float2(*(const __half2*)&g_eh[p1.x * EMB + lane * 2]);
        float2 e2 = __half22float2(*(const __half2*)&g_eh[p2.x * EMB + lane * 2]);
        float2 e3 = __half22float2(*(const __half2*)&g_eh[p3.x * EMB + lane * 2]);
        ax0 = fmaf(v0, e0.x, ax0); ay0 = fmaf(v0, e0.y, ay0);
        ax1 = fmaf(v1, e1.x, ax1); ay1 = fmaf(v1, e1.y, ay1);
        ax2 = fmaf(v2, e2.x, ax2); ay2 = fmaf(v2, e2.y, ay2);
        ax3 = fmaf(v3, e3.x, ax3); ay3 = fmaf(v3, e3.y, ay3);
    }
    for (; j < t; j++) {
        int2 pe = g_edge[j];
        float v = __int_as_float(pe.y);
        float2 ev = __half22float2(*(const __half2*)&g_eh[pe.x * EMB + lane * 2]);
        ax0 = fmaf(v, ev.x, ax0);
        ay0 = fmaf(v, ev.y, ay0);
    }
    *(float2*)&g_x[r * EMB + lane * 2] =
        make_float2((ax0 + ax1) + (ax2 + ax3), (ay0 + ay1) + (ay2 + ay3));
}

// ---------------- Dense: h = (e+x)@W1 + (x*e)@W2 + b1+b2; leaky; l2norm ------
// Interleaved-pair layout: sA[(row,d)] = float2(e+x, e*x); sW[(d,k)] = float2(W1,W2)
// at padded index k+(k>>3) -> bank-pair-conflict-free weight loads.
// One FFMA2 per (row,col,d) computes both part1 and part2 lanes.
#define A_STR 65   // float2 stride per A row (130 floats)
#define W_STR 72   // float2 stride per W d-row (64 + 8 pad)
__global__ void __launch_bounds__(256, 2)
k_dense(const float* __restrict__ W1, const float* __restrict__ b1,
        const float* __restrict__ W2, const float* __restrict__ b2,
        float* __restrict__ out, int last) {
    extern __shared__ float2 sm2[];
    float2* sA = sm2;                    // 128 * 65 float2
    float2* sW = sm2 + 128 * A_STR;      // 64 * 72 float2
    float*  sH = (float*)sA;             // reused for h (stride 130 floats)

    const int node0 = blockIdx.x * 128;
    const int tid = threadIdx.x;

    // interleave weights: sW[d][k] = (W1[d*64+k], W2[d*64+k]) with pad swizzle
    for (int i = tid; i < 4096; i += 256) {
        int d = i >> 6, k = i & 63;
        sW[d * W_STR + k + (k >> 3)] = make_float2(W1[i], W2[i]);
    }
    // build A tiles: (e+x, e*x) pairs
    for (int i = tid; i < 2048; i += 256) {
        int r  = i >> 4;
        int c4 = (i & 15) * 4;
        int n  = node0 + r;
        float4 ev = make_float4(0.f, 0.f, 0.f, 0.f);
        float4 xv = ev;
        if (n < N_NODES) {
            ev = *(const float4*)&g_e[n * EMB + c4];
            xv = *(const float4*)&g_x[n * EMB + c4];
        }
        float2* p = &sA[r * A_STR + c4];
        p[0] = make_float2(ev.x + xv.x, ev.x * xv.x);
        p[1] = make_float2(ev.y + xv.y, ev.y * xv.y);
        p[2] = make_float2(ev.z + xv.z, ev.z * xv.z);
        p[3] = make_float2(ev.w + xv.w, ev.w * xv.w);
    }
    __syncthreads();

    const int tn = (tid >> 3) * 4;        // node base (0..124)
    const int tk = (tid & 7) * 8;         // col base (0..56)
    const int wb = tk + (tk >> 3);        // padded weight base

    unsigned long long racc[4][8];        // [row][col] = (part1, part2)
    #pragma unroll
    for (int i = 0; i < 4; i++)
        #pragma unroll
        for (int p = 0; p < 8; p++) racc[i][p] = 0ull;

    #pragma unroll 2
    for (int d = 0; d < 64; d++) {
        const unsigned long long* wrow =
            (const unsigned long long*)(sW + d * W_STR + wb);
        unsigned long long wv[8];
        #pragma unroll
        for (int p = 0; p < 8; p++) wv[p] = wrow[p];
        #pragma unroll
        for (int i = 0; i < 4; i++) {
            unsigned long long ap =
                *(const unsigned long long*)(sA + (tn + i) * A_STR + d);
            #pragma unroll
            for (int p = 0; p < 8; p++)
                FMA_F32X2(racc[i][p], ap, wv[p], racc[i][p]);
        }
    }

    float bs[8];
    #pragma unroll
    for (int p = 0; p < 8; p++) bs[p] = b1[tk + p] + b2[tk + p];
    __syncthreads();   // all sA/sW reads complete before sH overwrite
    #pragma unroll
    for (int i = 0; i < 4; i++) {
        #pragma unroll
        for (int p = 0; p < 8; p++) {
            unsigned int lo, hi;
            UNPACK_F32X2(lo, hi, racc[i][p]);
            float h = __uint_as_float(lo) + __uint_as_float(hi) + bs[p];
            h = (h >= 0.f) ? h : NEG_SLOPE * h;
            sH[(tn + i) * 130 + tk + p] = h;
        }
    }
    __syncthreads();

    // per-row L2 normalize + update e, eh, acc (+ final output on last layer)
    int w = tid >> 5, lane = tid & 31;
    for (int rr = w; rr < 128; rr += 8) {
        int n = node0 + rr;
        float h0 = sH[rr * 130 + lane * 2];
        float h1 = sH[rr * 130 + lane * 2 + 1];
        float ss = h0 * h0 + h1 * h1;
        #pragma unroll
        for (int off = 16; off; off >>= 1) ss += __shfl_xor_sync(0xffffffffu, ss, off);
        float scale = 1.0f / fmaxf(sqrtf(ss), 1e-12f);
        if (n < N_NODES) {
            float e0 = h0 * scale, e1 = h1 * scale;
            float2 a = *(const float2*)&g_acc[n * EMB + lane * 2];
            float a0 = a.x + e0, a1 = a.y + e1;
            *(float2*)&g_e[n * EMB + lane * 2] = make_float2(e0, e1);
            *(__half2*)&g_eh[n * EMB + lane * 2] = __floats2half2_rn(e0, e1);
            if (last) {
                *(float2*)&out[n * EMB + lane * 2] = make_float2(a0 * 0.25f, a1 * 0.25f);
            } else {
                *(float2*)&g_acc[n * EMB + lane * 2] = make_float2(a0, a1);
            }
        }
    }
}

// ---------------- launch ----------------
extern "C" void kernel_launch(void* const* d_in, const int* in_sizes, int n_in,
                              void* d_out, int out_size) {
    const int*   edge_row = (const int*)d_in[0];
    const int*   edge_col = (const int*)d_in[1];
    const float* edge_val = (const float*)d_in[2];
    const float* user_emb = (const float*)d_in[3];
    const float* item_emb = (const float*)d_in[4];
    const float* W1 = (const float*)d_in[5];
    const float* b1 = (const float*)d_in[6];
    const float* W2 = (const float*)d_in[7];
    const float* b2 = (const float*)d_in[8];
    float* out = (float*)d_out;

    const int dense_smem = (128 * A_STR + 64 * W_STR) * (int)sizeof(float2); // 103424 B
    cudaFuncSetAttribute(k_dense, cudaFuncAttributeMaxDynamicSharedMemorySize, dense_smem);

    const int scan_blocks = (N_NODES + 511) / 512;  // 196

    k_init<<<(N_NODES * EMB / 4 + 255) / 256, 256>>>(user_emb, item_emb);
    k_hist<<<(N_EDGES + 255) / 256, 256>>>(edge_row);
    k_scan1<<<scan_blocks, 512>>>();
    k_scan3<<<scan_blocks, 512>>>();
    k_scatter<<<(N_EDGES + 255) / 256, 256>>>(edge_row, edge_col, edge_val);

    for (int layer = 0; layer < 3; layer++) {
        k_spmm<<<(N_NODES + 7) / 8, 256>>>();
        k_dense<<<(N_NODES + 127) / 128, 256, dense_smem>>>(
            W1 + layer * EMB * EMB, b1 + layer * EMB,
            W2 + layer * EMB * EMB, b2 + layer * EMB,
            out, layer == 2);
    }
    (void)in_sizes; (void)n_in; (void)out_size;
}